// round 5
// baseline (speedup 1.0000x reference)
#include <cuda_runtime.h>
#include <math.h>
#include <stdint.h>

#define DIM 128

// Scratch (static __device__ — no allocations allowed)
__device__ float  g_H[(100000 + 4096) * DIM];   // h = X_input @ W
__device__ int    g_pos[1000000];               // node -> in-batch position (or -1)
__device__ double g_acc[2];                     // [0] xb_norm sum, [1] info sum

// ---------------------------------------------------------------------------
// Init: out[0:B*128) = bias (broadcast per row)
__global__ __launch_bounds__(256) void k_init_out(float* __restrict__ out,
                                                  const float* __restrict__ bias,
                                                  int Bn) {
    int total = Bn * (DIM / 4);
    for (int i = blockIdx.x * blockDim.x + threadIdx.x; i < total;
         i += gridDim.x * blockDim.x) {
        float4 bv = ((const float4*)bias)[i & 31];
        ((float4*)out)[i] = bv;
    }
}

// Init: pos = -1, zero accumulators
__global__ __launch_bounds__(256) void k_init_pos(int n_total) {
    int i = blockIdx.x * blockDim.x + threadIdx.x;
    if (i == 0) { g_acc[0] = 0.0; g_acc[1] = 0.0; }
    for (; i < n_total; i += gridDim.x * blockDim.x) g_pos[i] = -1;
}

__global__ __launch_bounds__(256) void k_set_pos(const int* __restrict__ bidx, int Bn) {
    int i = blockIdx.x * blockDim.x + threadIdx.x;
    if (i < Bn) g_pos[bidx[i]] = i;
}

// ---------------------------------------------------------------------------
// tf32 helpers
__device__ __forceinline__ uint32_t f2tf32(float f) {
    uint32_t r;
    asm("cvt.rna.tf32.f32 %0, %1;" : "=r"(r) : "f"(f));
    return r;
}

__device__ __forceinline__ void mma_tf32(float c[4], const uint32_t a[4], const uint32_t b[2]) {
    asm volatile(
        "mma.sync.aligned.m16n8k8.row.col.f32.tf32.tf32.f32 "
        "{%0,%1,%2,%3},{%4,%5,%6,%7},{%8,%9},{%0,%1,%2,%3};"
        : "+f"(c[0]), "+f"(c[1]), "+f"(c[2]), "+f"(c[3])
        : "r"(a[0]), "r"(a[1]), "r"(a[2]), "r"(a[3]), "r"(b[0]), "r"(b[1]));
}

// ---------------------------------------------------------------------------
// GEMM (tf32 tensor core): g_H = [X_B ; codebook*wur] @ W   (Rn x 128)(128 x 128)
// CTA: 64 rows x 128 cols, 256 threads = 8 warps, warp tile 32x32.
// A tile tf32-converted into smem (pad 132: conflict-free fragment reads).
// W fragments loaded from global (64KB, L1-resident) with per-load tf32 cvt.
// xb_norm folded into the A-load phase (each warp loads whole rows).
__global__ __launch_bounds__(256) void k_gemm_tf32(const float* __restrict__ X_B,
                                                   const float* __restrict__ codebook,
                                                   const float* __restrict__ W,
                                                   const float* __restrict__ wur_p,
                                                   int Bn, int Rn) {
    __shared__ uint32_t As[64 * 132];
    __shared__ double s_norm;

    int tid  = threadIdx.x;
    int lane = tid & 31;
    int wid  = tid >> 5;
    int row0 = blockIdx.x * 64;
    float wur = *wur_p;

    if (tid == 0) s_norm = 0.0;

    // Load 64x128 tile; warp w loads rows v*8 + w (full row per iteration).
    double nsum = 0.0;
    #pragma unroll
    for (int v = 0; v < 8; v++) {
        int r    = v * 8 + wid;
        int grow = row0 + r;
        float4 x = make_float4(0.f, 0.f, 0.f, 0.f);
        if (grow < Bn) {
            x = ((const float4*)X_B)[(size_t)grow * 32 + lane];
            // fold xb_norm: warp-reduce sum of squares of this row
            float p = x.x * x.x + x.y * x.y + x.z * x.z + x.w * x.w;
            #pragma unroll
            for (int o = 16; o > 0; o >>= 1) p += __shfl_down_sync(0xffffffffu, p, o);
            if (lane == 0) nsum += sqrt((double)p);
        } else if (grow < Rn) {
            x = ((const float4*)codebook)[(size_t)(grow - Bn) * 32 + lane];
            x.x *= wur; x.y *= wur; x.z *= wur; x.w *= wur;
        }
        uint32_t* dst = &As[r * 132 + lane * 4];
        dst[0] = f2tf32(x.x);
        dst[1] = f2tf32(x.y);
        dst[2] = f2tf32(x.z);
        dst[3] = f2tf32(x.w);
    }
    __syncthreads();

    // Warp tiling: 2 warps along M (32 rows), 4 along N (32 cols)
    int mw = wid & 1;
    int nw = wid >> 1;
    int bm = mw * 32;           // smem row base
    int bn = nw * 32;           // col base

    float acc[2][4][4];
    #pragma unroll
    for (int t = 0; t < 2; t++)
        #pragma unroll
        for (int j = 0; j < 4; j++)
            #pragma unroll
            for (int q = 0; q < 4; q++) acc[t][j][q] = 0.f;

    int lr = lane >> 2;   // 0..7
    int lc = lane & 3;    // 0..3

    #pragma unroll
    for (int k0 = 0; k0 < DIM; k0 += 8) {
        uint32_t a[2][4];
        #pragma unroll
        for (int t = 0; t < 2; t++) {
            int ar = bm + t * 16 + lr;
            a[t][0] = As[ar * 132 + k0 + lc];
            a[t][1] = As[(ar + 8) * 132 + k0 + lc];
            a[t][2] = As[ar * 132 + k0 + 4 + lc];
            a[t][3] = As[(ar + 8) * 132 + k0 + 4 + lc];
        }
        uint32_t b[4][2];
        #pragma unroll
        for (int j = 0; j < 4; j++) {
            int bcol = bn + j * 8 + lr;
            b[j][0] = f2tf32(__ldg(&W[(size_t)(k0 + lc) * DIM + bcol]));
            b[j][1] = f2tf32(__ldg(&W[(size_t)(k0 + 4 + lc) * DIM + bcol]));
        }
        #pragma unroll
        for (int t = 0; t < 2; t++)
            #pragma unroll
            for (int j = 0; j < 4; j++)
                mma_tf32(acc[t][j], a[t], b[j]);
    }

    // Epilogue: store H
    #pragma unroll
    for (int t = 0; t < 2; t++) {
        int r0 = row0 + bm + t * 16 + lr;
        #pragma unroll
        for (int j = 0; j < 4; j++) {
            int c = bn + j * 8 + lc * 2;
            if (r0 < Rn)
                *(float2*)&g_H[(size_t)r0 * DIM + c] = make_float2(acc[t][j][0], acc[t][j][1]);
            if (r0 + 8 < Rn)
                *(float2*)&g_H[(size_t)(r0 + 8) * DIM + c] = make_float2(acc[t][j][2], acc[t][j][3]);
        }
    }

    // xb_norm block reduction -> global
    if (lane == 0 && nsum != 0.0) atomicAdd(&s_norm, nsum);
    __syncthreads();
    if (tid == 0 && s_norm != 0.0) atomicAdd(&g_acc[0], s_norm);
}

// ---------------------------------------------------------------------------
// Vector fp32 reduction to global (sm_90+)
__device__ __forceinline__ void red_add_v4(float* addr, float x, float y, float z, float w) {
    asm volatile("red.global.add.v4.f32 [%0], {%1, %2, %3, %4};"
                 :: "l"(addr), "f"(x), "f"(y), "f"(z), "f"(w) : "memory");
}

// Edge scatter: one warp per edge (grid-stride).
//   part 1: out[dst] += w * H[new_src]     (v4 atomic, L2-resident footprint)
//   part 2 (src out of batch): info += w * dot(H[dst], grad_cb[c])
__global__ __launch_bounds__(256) void k_scatter(const int*   __restrict__ edge_dst,
                                                 const int*   __restrict__ edge_src,
                                                 const float* __restrict__ ew,
                                                 const int*   __restrict__ c_idx,
                                                 const float* __restrict__ grad_cb,
                                                 float*       __restrict__ out,
                                                 int E, int Bn) {
    __shared__ double s_info;
    if (threadIdx.x == 0) s_info = 0.0;
    __syncthreads();

    int lane = threadIdx.x & 31;
    int wid  = threadIdx.x >> 5;
    int gw   = blockIdx.x * 8 + wid;
    int nw   = gridDim.x * 8;
    double local = 0.0;

    for (int e = gw; e < E; e += nw) {
        int   dst = edge_dst[e];
        int   src = edge_src[e];
        float w   = ew[e];
        int   sl  = g_pos[src];
        int   ns  = (sl >= 0) ? sl : (Bn + c_idx[src]);

        float4 h = *(const float4*)&g_H[(size_t)ns * DIM + lane * 4];
        red_add_v4(&out[(size_t)dst * DIM + lane * 4],
                   w * h.x, w * h.y, w * h.z, w * h.w);

        if (sl < 0) {   // uniform per warp (whole warp = one edge)
            int c = ns - Bn;
            float4 hd = *(const float4*)&g_H[(size_t)dst * DIM + lane * 4];
            float4 g  = *(const float4*)&grad_cb[(size_t)c * DIM + lane * 4];
            float p = hd.x * g.x + hd.y * g.y + hd.z * g.z + hd.w * g.w;
            #pragma unroll
            for (int o = 16; o > 0; o >>= 1) p += __shfl_down_sync(0xffffffffu, p, o);
            if (lane == 0) local += (double)w * (double)p;
        }
    }

    if (lane == 0) atomicAdd(&s_info, local);
    __syncthreads();
    if (threadIdx.x == 0) atomicAdd(&g_acc[1], s_info);
}

__global__ void k_finalize(float* __restrict__ out, const float* __restrict__ wur_p, int Bn) {
    if (threadIdx.x == 0 && blockIdx.x == 0) {
        out[(size_t)Bn * DIM]     = (float)(g_acc[0] / (double)Bn);
        out[(size_t)Bn * DIM + 1] = (float)(g_acc[1] * (double)(*wur_p));
    }
}

// ---------------------------------------------------------------------------
extern "C" void kernel_launch(void* const* d_in, const int* in_sizes, int n_in,
                              void* d_out, int out_size) {
    const float* X_B      = (const float*)d_in[0];
    const int*   edge_dst = (const int*)d_in[1];
    const int*   edge_src = (const int*)d_in[2];
    const float* ew       = (const float*)d_in[3];
    const int*   bidx     = (const int*)d_in[4];
    const int*   c_idx    = (const int*)d_in[5];
    const float* codebook = (const float*)d_in[6];
    const float* grad_cb  = (const float*)d_in[7];
    const float* W        = (const float*)d_in[8];
    const float* bias     = (const float*)d_in[9];
    const float* wur      = (const float*)d_in[10];
    float* out = (float*)d_out;

    int Bn = in_sizes[0] / DIM;   // 100000
    int E  = in_sizes[1];         // 500000
    int Nt = in_sizes[5];         // 1000000
    int Mn = in_sizes[6] / DIM;   // 4096
    int Rn = Bn + Mn;

    k_init_out<<<2048, 256>>>(out, bias, Bn);
    k_init_pos<<<2048, 256>>>(Nt);
    k_set_pos<<<(Bn + 255) / 256, 256>>>(bidx, Bn);
    k_gemm_tf32<<<(Rn + 63) / 64, 256>>>(X_B, codebook, W, wur, Bn, Rn);
    k_scatter<<<4096, 256>>>(edge_dst, edge_src, ew, c_idx, grad_cb, out, E, Bn);
    k_finalize<<<1, 32>>>(out, wur, Bn);
}

// round 6
// speedup vs baseline: 1.0075x; 1.0075x over previous
#include <cuda_runtime.h>
#include <math.h>
#include <stdint.h>

#define DIM 128

// Scratch (static __device__ — no allocations allowed)
__device__ float  g_H[(100000 + 4096) * DIM];   // h = X_input @ W
__device__ int    g_pos[1000000];               // node -> in-batch position (or -1)
__device__ double g_acc[2];                     // [0] xb_norm sum, [1] info sum

// ---------------------------------------------------------------------------
// Init: out[0:B*128) = bias (broadcast per row)
__global__ __launch_bounds__(256) void k_init_out(float* __restrict__ out,
                                                  const float* __restrict__ bias,
                                                  int Bn) {
    int total = Bn * (DIM / 4);
    for (int i = blockIdx.x * blockDim.x + threadIdx.x; i < total;
         i += gridDim.x * blockDim.x) {
        float4 bv = ((const float4*)bias)[i & 31];
        ((float4*)out)[i] = bv;
    }
}

// Init: pos = -1, zero accumulators
__global__ __launch_bounds__(256) void k_init_pos(int n_total) {
    int i = blockIdx.x * blockDim.x + threadIdx.x;
    if (i == 0) { g_acc[0] = 0.0; g_acc[1] = 0.0; }
    for (; i < n_total; i += gridDim.x * blockDim.x) g_pos[i] = -1;
}

__global__ __launch_bounds__(256) void k_set_pos(const int* __restrict__ bidx, int Bn) {
    int i = blockIdx.x * blockDim.x + threadIdx.x;
    if (i < Bn) g_pos[bidx[i]] = i;
}

// ---------------------------------------------------------------------------
// tf32 helpers
__device__ __forceinline__ uint32_t f2tf32(float f) {
    uint32_t r;
    asm("cvt.rna.tf32.f32 %0, %1;" : "=r"(r) : "f"(f));
    return r;
}

__device__ __forceinline__ void mma_tf32(float c[4], const uint32_t a[4], const uint32_t b[2]) {
    asm volatile(
        "mma.sync.aligned.m16n8k8.row.col.f32.tf32.tf32.f32 "
        "{%0,%1,%2,%3},{%4,%5,%6,%7},{%8,%9},{%0,%1,%2,%3};"
        : "+f"(c[0]), "+f"(c[1]), "+f"(c[2]), "+f"(c[3])
        : "r"(a[0]), "r"(a[1]), "r"(a[2]), "r"(a[3]), "r"(b[0]), "r"(b[1]));
}

// ---------------------------------------------------------------------------
// GEMM (tf32 tensor core): g_H = [X_B ; codebook*wur] @ W   (Rn x 128)(128 x 128)
// CTA: 64 rows x 128 cols, 256 threads = 8 warps, warp tile 32x32.
// A tile tf32-converted into smem (pad 132: conflict-free fragment reads).
// W fragments loaded from global (64KB, L1-resident) with per-load tf32 cvt.
// xb_norm folded into the A-load phase (each warp loads whole rows).
__global__ __launch_bounds__(256) void k_gemm_tf32(const float* __restrict__ X_B,
                                                   const float* __restrict__ codebook,
                                                   const float* __restrict__ W,
                                                   const float* __restrict__ wur_p,
                                                   int Bn, int Rn) {
    __shared__ uint32_t As[64 * 132];
    __shared__ double s_norm;

    int tid  = threadIdx.x;
    int lane = tid & 31;
    int wid  = tid >> 5;
    int row0 = blockIdx.x * 64;
    float wur = *wur_p;

    if (tid == 0) s_norm = 0.0;

    // Load 64x128 tile; warp w loads rows v*8 + w (full row per iteration).
    double nsum = 0.0;
    #pragma unroll
    for (int v = 0; v < 8; v++) {
        int r    = v * 8 + wid;
        int grow = row0 + r;
        float4 x = make_float4(0.f, 0.f, 0.f, 0.f);
        if (grow < Bn) {
            x = ((const float4*)X_B)[(size_t)grow * 32 + lane];
            // fold xb_norm: warp-reduce sum of squares of this row
            float p = x.x * x.x + x.y * x.y + x.z * x.z + x.w * x.w;
            #pragma unroll
            for (int o = 16; o > 0; o >>= 1) p += __shfl_down_sync(0xffffffffu, p, o);
            if (lane == 0) nsum += sqrt((double)p);
        } else if (grow < Rn) {
            x = ((const float4*)codebook)[(size_t)(grow - Bn) * 32 + lane];
            x.x *= wur; x.y *= wur; x.z *= wur; x.w *= wur;
        }
        uint32_t* dst = &As[r * 132 + lane * 4];
        dst[0] = f2tf32(x.x);
        dst[1] = f2tf32(x.y);
        dst[2] = f2tf32(x.z);
        dst[3] = f2tf32(x.w);
    }
    __syncthreads();

    // Warp tiling: 2 warps along M (32 rows), 4 along N (32 cols)
    int mw = wid & 1;
    int nw = wid >> 1;
    int bm = mw * 32;           // smem row base
    int bn = nw * 32;           // col base

    float acc[2][4][4];
    #pragma unroll
    for (int t = 0; t < 2; t++)
        #pragma unroll
        for (int j = 0; j < 4; j++)
            #pragma unroll
            for (int q = 0; q < 4; q++) acc[t][j][q] = 0.f;

    int lr = lane >> 2;   // 0..7
    int lc = lane & 3;    // 0..3

    #pragma unroll
    for (int k0 = 0; k0 < DIM; k0 += 8) {
        uint32_t a[2][4];
        #pragma unroll
        for (int t = 0; t < 2; t++) {
            int ar = bm + t * 16 + lr;
            a[t][0] = As[ar * 132 + k0 + lc];
            a[t][1] = As[(ar + 8) * 132 + k0 + lc];
            a[t][2] = As[ar * 132 + k0 + 4 + lc];
            a[t][3] = As[(ar + 8) * 132 + k0 + 4 + lc];
        }
        uint32_t b[4][2];
        #pragma unroll
        for (int j = 0; j < 4; j++) {
            int bcol = bn + j * 8 + lr;
            b[j][0] = f2tf32(__ldg(&W[(size_t)(k0 + lc) * DIM + bcol]));
            b[j][1] = f2tf32(__ldg(&W[(size_t)(k0 + 4 + lc) * DIM + bcol]));
        }
        #pragma unroll
        for (int t = 0; t < 2; t++)
            #pragma unroll
            for (int j = 0; j < 4; j++)
                mma_tf32(acc[t][j], a[t], b[j]);
    }

    // Epilogue: store H
    #pragma unroll
    for (int t = 0; t < 2; t++) {
        int r0 = row0 + bm + t * 16 + lr;
        #pragma unroll
        for (int j = 0; j < 4; j++) {
            int c = bn + j * 8 + lc * 2;
            if (r0 < Rn)
                *(float2*)&g_H[(size_t)r0 * DIM + c] = make_float2(acc[t][j][0], acc[t][j][1]);
            if (r0 + 8 < Rn)
                *(float2*)&g_H[(size_t)(r0 + 8) * DIM + c] = make_float2(acc[t][j][2], acc[t][j][3]);
        }
    }

    // xb_norm block reduction -> global
    if (lane == 0 && nsum != 0.0) atomicAdd(&s_norm, nsum);
    __syncthreads();
    if (tid == 0 && s_norm != 0.0) atomicAdd(&g_acc[0], s_norm);
}

// ---------------------------------------------------------------------------
// Vector fp32 reduction to global (sm_90+)
__device__ __forceinline__ void red_add_v4(float* addr, float x, float y, float z, float w) {
    asm volatile("red.global.add.v4.f32 [%0], {%1, %2, %3, %4};"
                 :: "l"(addr), "f"(x), "f"(y), "f"(z), "f"(w) : "memory");
}

// Edge scatter: one warp per edge (grid-stride).
//   part 1: out[dst] += w * H[new_src]     (v4 atomic, L2-resident footprint)
//   part 2 (src out of batch): info += w * dot(H[dst], grad_cb[c])
__global__ __launch_bounds__(256) void k_scatter(const int*   __restrict__ edge_dst,
                                                 const int*   __restrict__ edge_src,
                                                 const float* __restrict__ ew,
                                                 const int*   __restrict__ c_idx,
                                                 const float* __restrict__ grad_cb,
                                                 float*       __restrict__ out,
                                                 int E, int Bn) {
    __shared__ double s_info;
    if (threadIdx.x == 0) s_info = 0.0;
    __syncthreads();

    int lane = threadIdx.x & 31;
    int wid  = threadIdx.x >> 5;
    int gw   = blockIdx.x * 8 + wid;
    int nw   = gridDim.x * 8;
    double local = 0.0;

    for (int e = gw; e < E; e += nw) {
        int   dst = edge_dst[e];
        int   src = edge_src[e];
        float w   = ew[e];
        int   sl  = g_pos[src];
        int   ns  = (sl >= 0) ? sl : (Bn + c_idx[src]);

        float4 h = *(const float4*)&g_H[(size_t)ns * DIM + lane * 4];
        red_add_v4(&out[(size_t)dst * DIM + lane * 4],
                   w * h.x, w * h.y, w * h.z, w * h.w);

        if (sl < 0) {   // uniform per warp (whole warp = one edge)
            int c = ns - Bn;
            float4 hd = *(const float4*)&g_H[(size_t)dst * DIM + lane * 4];
            float4 g  = *(const float4*)&grad_cb[(size_t)c * DIM + lane * 4];
            float p = hd.x * g.x + hd.y * g.y + hd.z * g.z + hd.w * g.w;
            #pragma unroll
            for (int o = 16; o > 0; o >>= 1) p += __shfl_down_sync(0xffffffffu, p, o);
            if (lane == 0) local += (double)w * (double)p;
        }
    }

    if (lane == 0) atomicAdd(&s_info, local);
    __syncthreads();
    if (threadIdx.x == 0) atomicAdd(&g_acc[1], s_info);
}

__global__ void k_finalize(float* __restrict__ out, const float* __restrict__ wur_p, int Bn) {
    if (threadIdx.x == 0 && blockIdx.x == 0) {
        out[(size_t)Bn * DIM]     = (float)(g_acc[0] / (double)Bn);
        out[(size_t)Bn * DIM + 1] = (float)(g_acc[1] * (double)(*wur_p));
    }
}

// ---------------------------------------------------------------------------
extern "C" void kernel_launch(void* const* d_in, const int* in_sizes, int n_in,
                              void* d_out, int out_size) {
    const float* X_B      = (const float*)d_in[0];
    const int*   edge_dst = (const int*)d_in[1];
    const int*   edge_src = (const int*)d_in[2];
    const float* ew       = (const float*)d_in[3];
    const int*   bidx     = (const int*)d_in[4];
    const int*   c_idx    = (const int*)d_in[5];
    const float* codebook = (const float*)d_in[6];
    const float* grad_cb  = (const float*)d_in[7];
    const float* W        = (const float*)d_in[8];
    const float* bias     = (const float*)d_in[9];
    const float* wur      = (const float*)d_in[10];
    float* out = (float*)d_out;

    int Bn = in_sizes[0] / DIM;   // 100000
    int E  = in_sizes[1];         // 500000
    int Nt = in_sizes[5];         // 1000000
    int Mn = in_sizes[6] / DIM;   // 4096
    int Rn = Bn + Mn;

    k_init_out<<<2048, 256>>>(out, bias, Bn);
    k_init_pos<<<2048, 256>>>(Nt);
    k_set_pos<<<(Bn + 255) / 256, 256>>>(bidx, Bn);
    k_gemm_tf32<<<(Rn + 63) / 64, 256>>>(X_B, codebook, W, wur, Bn, Rn);
    k_scatter<<<4096, 256>>>(edge_dst, edge_src, ew, c_idx, grad_cb, out, E, Bn);
    k_finalize<<<1, 32>>>(out, wur, Bn);
}